// round 14
// baseline (speedup 1.0000x reference)
#include <cuda_runtime.h>
#include <cuda_bf16.h>
#include <cstdint>

#define HH 768
#define WW 768
#define HW (768*768)
#define IP 769                 // integral image pitch (769x769 per channel)
#define IPP (769*769)

// ---------------- scratch (device globals: allocation-free) ----------------
// NHWC bf16 hi/lo records, 128B/px: 16 hi words then 16 lo words, word order
// permuted as [p0,p4,p1,p5,p2,p6,p3,p7, p8,p12,p9,p13,p10,p14,p11,p15]
// (pq = channel pair (2q,2q+1)) so mma fragment loads are single LDS.64s.
__device__ __align__(16) unsigned char g_featB[(size_t)HW * 128];  // 75.5 MB
__device__ float g_integ[64u * IPP];          // conv2 output + integral image (151 MB)

// ---------------- conv1: 3->32, 3x3, pad 1, fused bias+relu+bn1 ----------------
__global__ __launch_bounds__(256) void conv1_k(
    const float* __restrict__ img, const float* __restrict__ w,
    const float* __restrict__ bias, const float* __restrict__ gg,
    const float* __restrict__ bb, const float* __restrict__ mm,
    const float* __restrict__ vv)
{
    __shared__ __align__(16) float s_in[3][18][18];
    __shared__ __align__(16) float s_w[27 * 32];
    __shared__ float s_scale[32], s_shift[32], s_bias[32];

    const int tx = threadIdx.x, ty = threadIdx.y;
    const int tid = ty * 16 + tx;

    for (int i = tid; i < 864; i += 256) {
        int o = i / 27, r = i % 27;
        s_w[r * 32 + o] = w[i];
    }
    if (tid < 32) {
        float sc = gg[tid] * rsqrtf(vv[tid] + 1e-5f);
        s_scale[tid] = sc;
        s_shift[tid] = bb[tid] - mm[tid] * sc;
        s_bias[tid]  = bias[tid];
    }
    const int bx0 = blockIdx.x * 16 - 1, by0 = blockIdx.y * 16 - 1;
    for (int i = tid; i < 3 * 324; i += 256) {
        int c = i / 324, r = i % 324, yy = r / 18, xx = r % 18;
        int gy = by0 + yy, gx = bx0 + xx;
        float val = (gy >= 0 && gy < HH && gx >= 0 && gx < WW)
                        ? img[c * HW + gy * WW + gx] : 0.f;
        s_in[c][yy][xx] = val;
    }
    __syncthreads();

    float acc[32];
    #pragma unroll
    for (int o = 0; o < 32; o++) acc[o] = s_bias[o];

    #pragma unroll 1
    for (int c = 0; c < 3; c++) {
        #pragma unroll
        for (int t = 0; t < 9; t++) {
            float vr = s_in[c][ty + t / 3][tx + t % 3];
            const float4* wp = (const float4*)&s_w[(c * 9 + t) * 32];
            #pragma unroll
            for (int q = 0; q < 8; q++) {
                float4 ww = wp[q];
                acc[4*q+0] = fmaf(vr, ww.x, acc[4*q+0]);
                acc[4*q+1] = fmaf(vr, ww.y, acc[4*q+1]);
                acc[4*q+2] = fmaf(vr, ww.z, acc[4*q+2]);
                acc[4*q+3] = fmaf(vr, ww.w, acc[4*q+3]);
            }
        }
    }

    const int y = blockIdx.y * 16 + ty, x = blockIdx.x * 16 + tx;
    // bn+relu, split fp32 -> bf16 hi + lo, pack pairs, write permuted record
    uint32_t ph[16], pl[16];
    #pragma unroll
    for (int q = 0; q < 16; q++) {
        float r0 = fmaxf(acc[2*q],   0.f) * s_scale[2*q]   + s_shift[2*q];
        float r1 = fmaxf(acc[2*q+1], 0.f) * s_scale[2*q+1] + s_shift[2*q+1];
        __nv_bfloat16 h0 = __float2bfloat16(r0);
        __nv_bfloat16 h1 = __float2bfloat16(r1);
        __nv_bfloat16 l0 = __float2bfloat16(r0 - __bfloat162float(h0));
        __nv_bfloat16 l1 = __float2bfloat16(r1 - __bfloat162float(h1));
        ph[q] = (uint32_t)__bfloat16_as_ushort(h0) | ((uint32_t)__bfloat16_as_ushort(h1) << 16);
        pl[q] = (uint32_t)__bfloat16_as_ushort(l0) | ((uint32_t)__bfloat16_as_ushort(l1) << 16);
    }
    uint4* rec = (uint4*)(g_featB + ((size_t)(y * WW + x) << 7));
    rec[0] = make_uint4(ph[0],  ph[4],  ph[1],  ph[5]);
    rec[1] = make_uint4(ph[2],  ph[6],  ph[3],  ph[7]);
    rec[2] = make_uint4(ph[8],  ph[12], ph[9],  ph[13]);
    rec[3] = make_uint4(ph[10], ph[14], ph[11], ph[15]);
    rec[4] = make_uint4(pl[0],  pl[4],  pl[1],  pl[5]);
    rec[5] = make_uint4(pl[2],  pl[6],  pl[3],  pl[7]);
    rec[6] = make_uint4(pl[8],  pl[12], pl[9],  pl[13]);
    rec[7] = make_uint4(pl[10], pl[14], pl[11], pl[15]);
}

// ---------------- zero integral-image borders ----------------
__global__ void zborder_row_k() {
    int i = blockIdx.x * 256 + threadIdx.x;
    if (i >= 64 * IP) return;
    int c = i / IP, k = i % IP;
    g_integ[(size_t)c * IPP + k] = 0.f;
}
__global__ void zborder_col_k() {
    int i = blockIdx.x * 256 + threadIdx.x;
    if (i >= 64 * IP) return;
    int c = i / IP, k = i % IP;
    g_integ[(size_t)c * IPP + (size_t)k * IP] = 0.f;
}

// ---------------- conv2 v8: mma.sync implicit GEMM, 16 warps/CTA ----------
// CTA 512 thr = 16 warps; output tile 128px x 4 rows. Warp-tile 16px x 32oc:
// warp w -> pixel col (w&7)*16, oc half (w>>3)*32. 4 warps/SMSP for latency
// cover (was 2). A smem: 6 rows x 130 px x 160B (hi|lo|pad). B: 9 taps x
// 64 oc x 160B. 3 passes x 9 taps x 2 ks x 4 nt mma.m16n8k16, fp32 accum.
#define A_RSTRIDE (130*160)
#define SM_A  0
#define SM_B  (6*A_RSTRIDE)                 // 124800
#define SM_BN (SM_B + 9*64*160)             // 216960
#define SMEM_DYN (SM_BN + 768)              // 217728

__global__ __launch_bounds__(512) void conv2_k(
    const float* __restrict__ w, const float* __restrict__ bias,
    const float* __restrict__ gg, const float* __restrict__ bb,
    const float* __restrict__ mm, const float* __restrict__ vv)
{
    extern __shared__ __align__(16) char sm[];
    const int tid = threadIdx.x, lane = tid & 31, wid = tid >> 5;
    const int x0 = blockIdx.x * 128, y0 = blockIdx.y * 4;

    if (tid < 64) {
        float sc = gg[tid] * rsqrtf(vv[tid] + 1e-5f);
        float* bn = (float*)(sm + SM_BN);
        bn[tid]       = bias[tid];
        bn[64 + tid]  = sc;
        bn[128 + tid] = bb[tid] - mm[tid] * sc;
    }

    // ---- stage A: 6 rows x 130 px, straight 16B copies (perm done by conv1) ----
    for (int i = tid; i < 6 * 130 * 8; i += 512) {
        int r = i / 1040, rem = i - r * 1040, p = rem >> 3, u = rem & 7;
        int gy = y0 - 1 + r, gx = x0 - 1 + p;
        uint4 val = make_uint4(0, 0, 0, 0);
        if ((unsigned)gy < HH && (unsigned)gx < WW)
            val = *(const uint4*)(g_featB + (((size_t)(gy * WW + gx)) << 7) + (u << 4));
        *(uint4*)(sm + SM_A + r * A_RSTRIDE + p * 160 + u * 16) = val;
    }

    // ---- stage B: w[oc][ci][tap] fp32 -> [tap][oc][perm ch] bf16 hi|lo ----
    for (int i = tid; i < 64 * 288; i += 512) {
        int o = i / 288, r = i - o * 288, c = r / 9, t = r - c * 9;
        float v = w[i];
        __nv_bfloat16 h = __float2bfloat16(v);
        __nv_bfloat16 l = __float2bfloat16(v - __bfloat162float(h));
        int boff = ((c >> 4) << 5) + (((c & 7) >> 1) << 3)
                 + (((c & 1) + ((c >> 3) & 1) * 2) << 1);
        char* dst = sm + SM_B + (t * 64 + o) * 160 + boff;
        *(__nv_bfloat16*)dst        = h;
        *(__nv_bfloat16*)(dst + 64) = l;
    }
    __syncthreads();

    const int gid = lane >> 2, qid = lane & 3;
    const int P0 = (wid & 7) * 16;          // pixel-column base
    const int OCB = (wid >> 3) * 32;        // oc base (0 or 32)
    const float* bn = (const float*)(sm + SM_BN);

    #pragma unroll 1
    for (int ry = 0; ry < 4; ry++) {
        float acc[4][4];
        #pragma unroll
        for (int nt = 0; nt < 4; nt++)
            #pragma unroll
            for (int q = 0; q < 4; q++) acc[nt][q] = 0.f;

        #pragma unroll 1
        for (int pass = 0; pass < 3; pass++) {
            const int Aoff = (pass == 1) ? 64 : 0;
            const int Boff = (pass == 2) ? 64 : 0;
            #pragma unroll 1
            for (int t = 0; t < 9; t++) {
                const char* abase = sm + SM_A + (ry + t / 3) * A_RSTRIDE
                                  + (P0 + (t % 3) + gid) * 160 + Aoff + qid * 8;
                const char* bbase = sm + SM_B + (t * 64 + OCB + gid) * 160 + Boff + qid * 8;
                #pragma unroll
                for (int ks = 0; ks < 2; ks++) {
                    uint2 a02 = *(const uint2*)(abase + ks * 32);            // a0, a2
                    uint2 a13 = *(const uint2*)(abase + ks * 32 + 8 * 160);  // a1, a3
                    #pragma unroll
                    for (int nt = 0; nt < 4; nt++) {
                        uint2 b = *(const uint2*)(bbase + ks * 32 + nt * 8 * 160);
                        asm("mma.sync.aligned.m16n8k16.row.col.f32.bf16.bf16.f32 "
                            "{%0,%1,%2,%3}, {%4,%5,%6,%7}, {%8,%9}, {%0,%1,%2,%3};"
                            : "+f"(acc[nt][0]), "+f"(acc[nt][1]),
                              "+f"(acc[nt][2]), "+f"(acc[nt][3])
                            : "r"(a02.x), "r"(a13.x), "r"(a02.y), "r"(a13.y),
                              "r"(b.x), "r"(b.y));
                    }
                }
            }
        }

        // epilogue: c0,c1 -> px gid; c2,c3 -> px gid+8; oc = OCB + nt*8 + qid*2
        const int pxa = x0 + P0 + gid, pxb = pxa + 8;
        const size_t rbase = (size_t)(y0 + ry + 1) * IP + 1;
        #pragma unroll
        for (int nt = 0; nt < 4; nt++) {
            int oc0 = OCB + nt * 8 + qid * 2;
            float b0 = bn[oc0],       b1 = bn[oc0 + 1];
            float s0 = bn[64 + oc0],  s1 = bn[64 + oc0 + 1];
            float h0 = bn[128 + oc0], h1 = bn[128 + oc0 + 1];
            g_integ[(size_t)oc0       * IPP + rbase + pxa] = fmaxf(acc[nt][0] + b0, 0.f) * s0 + h0;
            g_integ[(size_t)(oc0 + 1) * IPP + rbase + pxa] = fmaxf(acc[nt][1] + b1, 0.f) * s1 + h1;
            g_integ[(size_t)oc0       * IPP + rbase + pxb] = fmaxf(acc[nt][2] + b0, 0.f) * s0 + h0;
            g_integ[(size_t)(oc0 + 1) * IPP + rbase + pxb] = fmaxf(acc[nt][3] + b1, 0.f) * s1 + h1;
        }
    }
}

// ---------------- row-wise inclusive scan (x), fp32, coalesced ----------------
__global__ __launch_bounds__(256) void rowscan_k() {
    const int warp = threadIdx.x >> 5, lane = threadIdx.x & 31;
    const int row = blockIdx.x * 8 + warp;
    const int c = row / HH, y = row % HH + 1;
    float* p = g_integ + (size_t)c * IPP + (size_t)y * IP + 1;

    float v[24];
    #pragma unroll
    for (int i = 0; i < 24; i++) v[i] = p[i * 32 + lane];

    float carry = 0.f;
    #pragma unroll
    for (int i = 0; i < 24; i++) {
        float x = v[i];
        #pragma unroll
        for (int d = 1; d < 32; d <<= 1) {
            float n = __shfl_up_sync(0xffffffffu, x, d);
            if (lane >= d) x += n;
        }
        x += carry;
        carry = __shfl_sync(0xffffffffu, x, 31);
        v[i] = x;
    }

    #pragma unroll
    for (int i = 0; i < 24; i++) p[i * 32 + lane] = v[i];
}

// ---------------- column-wise inclusive scan (y), fp32 ----------------
__global__ __launch_bounds__(256) void colscan_k() {
    int idx = blockIdx.x * 256 + threadIdx.x;
    if (idx >= 64 * WW) return;
    int c = idx / WW, x = idx % WW + 1;
    float* p = g_integ + (size_t)c * IPP + x;
    float s = 0.f;
    #pragma unroll 8
    for (int y = 1; y <= HH; y++) {
        s += p[(size_t)y * IP];
        p[(size_t)y * IP] = s;
    }
}

// ---------------- ROI pool + FC1(relu) + FC2 ----------------
__global__ __launch_bounds__(128) void roi_fc_k(
    const int* __restrict__ boxes,
    const float* __restrict__ fc1w, const float* __restrict__ fc1b,
    const float* __restrict__ fc2w, const float* __restrict__ fc2b,
    float* __restrict__ out)
{
    __shared__ float s_pool[1600];
    __shared__ float s_h1[128];
    __shared__ int sy0[5], sy1[5], sx0[5], sx1[5];

    const int b = blockIdx.x, tid = threadIdx.x;
    if (tid < 5) {
        int xmin = boxes[b*4+0], ymin = boxes[b*4+1];
        int xmax = boxes[b*4+2], ymax = boxes[b*4+3];
        int bh = ymax - ymin, bw = xmax - xmin;
        sy0[tid] = ymin + tid * bh / 5;
        sy1[tid] = ymin + ((tid + 1) * bh + 4) / 5;
        sx0[tid] = xmin + tid * bw / 5;
        sx1[tid] = xmin + ((tid + 1) * bw + 4) / 5;
    }
    __syncthreads();

    for (int idx = tid; idx < 1600; idx += 128) {
        int c = idx / 25, r = idx % 25, i = r / 5, j = r % 5;
        const float* I = g_integ + (size_t)c * IPP;
        double s = (double)I[(size_t)sy1[i] * IP + sx1[j]] - (double)I[(size_t)sy0[i] * IP + sx1[j]]
                 - (double)I[(size_t)sy1[i] * IP + sx0[j]] + (double)I[(size_t)sy0[i] * IP + sx0[j]];
        double area = (double)((sy1[i] - sy0[i]) * (sx1[j] - sx0[j]));
        s_pool[idx] = (float)(s / area);
    }
    __syncthreads();

    const int warp = tid >> 5, lane = tid & 31;
    for (int o = warp; o < 128; o += 4) {
        const float* wr = fc1w + o * 1600;
        float sum = 0.f;
        for (int k = lane; k < 1600; k += 32) sum = fmaf(wr[k], s_pool[k], sum);
        #pragma unroll
        for (int d = 16; d; d >>= 1) sum += __shfl_down_sync(0xffffffffu, sum, d);
        if (lane == 0) s_h1[o] = fmaxf(sum + fc1b[o], 0.f);
    }
    __syncthreads();

    {
        int o = warp;
        float sum = 0.f;
        #pragma unroll
        for (int k = lane; k < 128; k += 32) sum = fmaf(fc2w[o * 128 + k], s_h1[k], sum);
        #pragma unroll
        for (int d = 16; d; d >>= 1) sum += __shfl_down_sync(0xffffffffu, sum, d);
        if (lane == 0) out[b * 4 + o] = sum + fc2b[o];
    }
}

// ---------------- launch ----------------
extern "C" void kernel_launch(void* const* d_in, const int* in_sizes, int n_in,
                              void* d_out, int out_size)
{
    const float* image = (const float*)d_in[0];
    const int*   boxes = (const int*)  d_in[1];
    const float* c1w = (const float*)d_in[2];
    const float* c1b = (const float*)d_in[3];
    const float* b1g = (const float*)d_in[4];
    const float* b1b = (const float*)d_in[5];
    const float* b1m = (const float*)d_in[6];
    const float* b1v = (const float*)d_in[7];
    const float* c2w = (const float*)d_in[8];
    const float* c2b = (const float*)d_in[9];
    const float* b2g = (const float*)d_in[10];
    const float* b2b = (const float*)d_in[11];
    const float* b2m = (const float*)d_in[12];
    const float* b2v = (const float*)d_in[13];
    const float* f1w = (const float*)d_in[14];
    const float* f1b = (const float*)d_in[15];
    const float* f2w = (const float*)d_in[16];
    const float* f2b = (const float*)d_in[17];
    float* out = (float*)d_out;

    cudaFuncSetAttribute(conv2_k, cudaFuncAttributeMaxDynamicSharedMemorySize, SMEM_DYN);

    conv1_k<<<dim3(48, 48), dim3(16, 16)>>>(image, c1w, c1b, b1g, b1b, b1m, b1v);
    zborder_row_k<<<(64 * IP + 255) / 256, 256>>>();
    zborder_col_k<<<(64 * IP + 255) / 256, 256>>>();
    conv2_k<<<dim3(6, 192), 512, SMEM_DYN>>>(c2w, c2b, b2g, b2b, b2m, b2v);  // profiled slot
    rowscan_k<<<64 * HH / 8, 256>>>();
    colscan_k<<<(64 * WW + 255) / 256, 256>>>();
    roi_fc_k<<<512, 128>>>(boxes, f1w, f1b, f2w, f2b, out);
}

// round 15
// speedup vs baseline: 1.1105x; 1.1105x over previous
#include <cuda_runtime.h>
#include <cuda_bf16.h>
#include <cstdint>

#define HH 768
#define WW 768
#define HW (768*768)
#define IP 769                 // integral image pitch (769x769 per channel)
#define IPP (769*769)

// ---------------- scratch (device globals: allocation-free) ----------------
// NHWC bf16 hi/lo records, 128B/px: 16 hi words then 16 lo words, word order
// permuted as [p0,p4,p1,p5,p2,p6,p3,p7, p8,p12,p9,p13,p10,p14,p11,p15]
// (pq = channel pair (2q,2q+1)) so mma fragment loads are single LDS.64s.
__device__ __align__(16) unsigned char g_featB[(size_t)HW * 128];  // 75.5 MB
__device__ float g_integ[64u * IPP];          // conv2 output + integral image (151 MB)

// ---------------- conv1: 3->32, 3x3, pad 1, fused bias+relu+bn1 ----------------
__global__ __launch_bounds__(256) void conv1_k(
    const float* __restrict__ img, const float* __restrict__ w,
    const float* __restrict__ bias, const float* __restrict__ gg,
    const float* __restrict__ bb, const float* __restrict__ mm,
    const float* __restrict__ vv)
{
    __shared__ __align__(16) float s_in[3][18][18];
    __shared__ __align__(16) float s_w[27 * 32];
    __shared__ float s_scale[32], s_shift[32], s_bias[32];

    const int tx = threadIdx.x, ty = threadIdx.y;
    const int tid = ty * 16 + tx;

    for (int i = tid; i < 864; i += 256) {
        int o = i / 27, r = i % 27;
        s_w[r * 32 + o] = w[i];
    }
    if (tid < 32) {
        float sc = gg[tid] * rsqrtf(vv[tid] + 1e-5f);
        s_scale[tid] = sc;
        s_shift[tid] = bb[tid] - mm[tid] * sc;
        s_bias[tid]  = bias[tid];
    }
    const int bx0 = blockIdx.x * 16 - 1, by0 = blockIdx.y * 16 - 1;
    for (int i = tid; i < 3 * 324; i += 256) {
        int c = i / 324, r = i % 324, yy = r / 18, xx = r % 18;
        int gy = by0 + yy, gx = bx0 + xx;
        float val = (gy >= 0 && gy < HH && gx >= 0 && gx < WW)
                        ? img[c * HW + gy * WW + gx] : 0.f;
        s_in[c][yy][xx] = val;
    }
    __syncthreads();

    float acc[32];
    #pragma unroll
    for (int o = 0; o < 32; o++) acc[o] = s_bias[o];

    #pragma unroll 1
    for (int c = 0; c < 3; c++) {
        #pragma unroll
        for (int t = 0; t < 9; t++) {
            float vr = s_in[c][ty + t / 3][tx + t % 3];
            const float4* wp = (const float4*)&s_w[(c * 9 + t) * 32];
            #pragma unroll
            for (int q = 0; q < 8; q++) {
                float4 ww = wp[q];
                acc[4*q+0] = fmaf(vr, ww.x, acc[4*q+0]);
                acc[4*q+1] = fmaf(vr, ww.y, acc[4*q+1]);
                acc[4*q+2] = fmaf(vr, ww.z, acc[4*q+2]);
                acc[4*q+3] = fmaf(vr, ww.w, acc[4*q+3]);
            }
        }
    }

    const int y = blockIdx.y * 16 + ty, x = blockIdx.x * 16 + tx;
    // bn+relu, split fp32 -> bf16 hi + lo, pack pairs, write permuted record
    uint32_t ph[16], pl[16];
    #pragma unroll
    for (int q = 0; q < 16; q++) {
        float r0 = fmaxf(acc[2*q],   0.f) * s_scale[2*q]   + s_shift[2*q];
        float r1 = fmaxf(acc[2*q+1], 0.f) * s_scale[2*q+1] + s_shift[2*q+1];
        __nv_bfloat16 h0 = __float2bfloat16(r0);
        __nv_bfloat16 h1 = __float2bfloat16(r1);
        __nv_bfloat16 l0 = __float2bfloat16(r0 - __bfloat162float(h0));
        __nv_bfloat16 l1 = __float2bfloat16(r1 - __bfloat162float(h1));
        ph[q] = (uint32_t)__bfloat16_as_ushort(h0) | ((uint32_t)__bfloat16_as_ushort(h1) << 16);
        pl[q] = (uint32_t)__bfloat16_as_ushort(l0) | ((uint32_t)__bfloat16_as_ushort(l1) << 16);
    }
    uint4* rec = (uint4*)(g_featB + ((size_t)(y * WW + x) << 7));
    rec[0] = make_uint4(ph[0],  ph[4],  ph[1],  ph[5]);
    rec[1] = make_uint4(ph[2],  ph[6],  ph[3],  ph[7]);
    rec[2] = make_uint4(ph[8],  ph[12], ph[9],  ph[13]);
    rec[3] = make_uint4(ph[10], ph[14], ph[11], ph[15]);
    rec[4] = make_uint4(pl[0],  pl[4],  pl[1],  pl[5]);
    rec[5] = make_uint4(pl[2],  pl[6],  pl[3],  pl[7]);
    rec[6] = make_uint4(pl[8],  pl[12], pl[9],  pl[13]);
    rec[7] = make_uint4(pl[10], pl[14], pl[11], pl[15]);
}

// ---------------- zero integral-image borders ----------------
__global__ void zborder_row_k() {
    int i = blockIdx.x * 256 + threadIdx.x;
    if (i >= 64 * IP) return;
    int c = i / IP, k = i % IP;
    g_integ[(size_t)c * IPP + k] = 0.f;
}
__global__ void zborder_col_k() {
    int i = blockIdx.x * 256 + threadIdx.x;
    if (i >= 64 * IP) return;
    int c = i / IP, k = i % IP;
    g_integ[(size_t)c * IPP + (size_t)k * IP] = 0.f;
}

// ---------------- conv2 v9: mma.sync implicit GEMM, fused-pass mainloop ------
// v7 shape (8 warps, warp-tile 16px x 64oc) but the 3 precision passes are
// fused per (tap,ks): load A_hi,A_lo (4 LDS) + B_hi,B_lo x 8nt (16 LDS) once,
// issue all 24 MMAs. LDS count per ry: 540 -> 360 (smem crossbar was the
// binding pipe at L1=72%).
#define A_RSTRIDE (130*160)
#define SM_A  0
#define SM_B  (6*A_RSTRIDE)                 // 124800
#define SM_BN (SM_B + 9*64*160)             // 216960
#define SMEM_DYN (SM_BN + 768)              // 217728

__global__ __launch_bounds__(256) void conv2_k(
    const float* __restrict__ w, const float* __restrict__ bias,
    const float* __restrict__ gg, const float* __restrict__ bb,
    const float* __restrict__ mm, const float* __restrict__ vv)
{
    extern __shared__ __align__(16) char sm[];
    const int tid = threadIdx.x, lane = tid & 31, wid = tid >> 5;
    const int x0 = blockIdx.x * 128, y0 = blockIdx.y * 4;

    if (tid < 64) {
        float sc = gg[tid] * rsqrtf(vv[tid] + 1e-5f);
        float* bn = (float*)(sm + SM_BN);
        bn[tid]       = bias[tid];
        bn[64 + tid]  = sc;
        bn[128 + tid] = bb[tid] - mm[tid] * sc;
    }

    // ---- stage A: 6 rows x 130 px, straight 16B copies (perm done by conv1) ----
    for (int i = tid; i < 6 * 130 * 8; i += 256) {
        int r = i / 1040, rem = i - r * 1040, p = rem >> 3, u = rem & 7;
        int gy = y0 - 1 + r, gx = x0 - 1 + p;
        uint4 val = make_uint4(0, 0, 0, 0);
        if ((unsigned)gy < HH && (unsigned)gx < WW)
            val = *(const uint4*)(g_featB + (((size_t)(gy * WW + gx)) << 7) + (u << 4));
        *(uint4*)(sm + SM_A + r * A_RSTRIDE + p * 160 + u * 16) = val;
    }

    // ---- stage B: w[oc][ci][tap] fp32 -> [tap][oc][perm ch] bf16 hi|lo ----
    for (int i = tid; i < 64 * 288; i += 256) {
        int o = i / 288, r = i - o * 288, c = r / 9, t = r - c * 9;
        float v = w[i];
        __nv_bfloat16 h = __float2bfloat16(v);
        __nv_bfloat16 l = __float2bfloat16(v - __bfloat162float(h));
        int boff = ((c >> 4) << 5) + (((c & 7) >> 1) << 3)
                 + (((c & 1) + ((c >> 3) & 1) * 2) << 1);
        char* dst = sm + SM_B + (t * 64 + o) * 160 + boff;
        *(__nv_bfloat16*)dst        = h;
        *(__nv_bfloat16*)(dst + 64) = l;
    }
    __syncthreads();

    const int gid = lane >> 2, qid = lane & 3;
    const int P0 = wid * 16;
    const float* bn = (const float*)(sm + SM_BN);

    #pragma unroll 1
    for (int ry = 0; ry < 4; ry++) {
        float acc[8][4];
        #pragma unroll
        for (int nt = 0; nt < 8; nt++)
            #pragma unroll
            for (int q = 0; q < 4; q++) acc[nt][q] = 0.f;

        #pragma unroll 1
        for (int t = 0; t < 9; t++) {
            const char* abase = sm + SM_A + (ry + t / 3) * A_RSTRIDE
                              + (P0 + (t % 3) + gid) * 160 + qid * 8;
            const char* bbase = sm + SM_B + (t * 64 + gid) * 160 + qid * 8;
            #pragma unroll
            for (int ks = 0; ks < 2; ks++) {
                // A fragments: hi (offset 0) and lo (offset 64)
                uint2 ah02 = *(const uint2*)(abase + ks * 32);
                uint2 ah13 = *(const uint2*)(abase + ks * 32 + 8 * 160);
                uint2 al02 = *(const uint2*)(abase + 64 + ks * 32);
                uint2 al13 = *(const uint2*)(abase + 64 + ks * 32 + 8 * 160);
                // B fragments: hi and lo for all 8 n-tiles
                uint2 bh[8], bl[8];
                #pragma unroll
                for (int nt = 0; nt < 8; nt++) {
                    bh[nt] = *(const uint2*)(bbase + ks * 32 + nt * 8 * 160);
                    bl[nt] = *(const uint2*)(bbase + 64 + ks * 32 + nt * 8 * 160);
                }
                #pragma unroll
                for (int nt = 0; nt < 8; nt++) {
                    asm("mma.sync.aligned.m16n8k16.row.col.f32.bf16.bf16.f32 "
                        "{%0,%1,%2,%3}, {%4,%5,%6,%7}, {%8,%9}, {%0,%1,%2,%3};"
                        : "+f"(acc[nt][0]), "+f"(acc[nt][1]),
                          "+f"(acc[nt][2]), "+f"(acc[nt][3])
                        : "r"(ah02.x), "r"(ah13.x), "r"(ah02.y), "r"(ah13.y),
                          "r"(bh[nt].x), "r"(bh[nt].y));
                    asm("mma.sync.aligned.m16n8k16.row.col.f32.bf16.bf16.f32 "
                        "{%0,%1,%2,%3}, {%4,%5,%6,%7}, {%8,%9}, {%0,%1,%2,%3};"
                        : "+f"(acc[nt][0]), "+f"(acc[nt][1]),
                          "+f"(acc[nt][2]), "+f"(acc[nt][3])
                        : "r"(al02.x), "r"(al13.x), "r"(al02.y), "r"(al13.y),
                          "r"(bh[nt].x), "r"(bh[nt].y));
                    asm("mma.sync.aligned.m16n8k16.row.col.f32.bf16.bf16.f32 "
                        "{%0,%1,%2,%3}, {%4,%5,%6,%7}, {%8,%9}, {%0,%1,%2,%3};"
                        : "+f"(acc[nt][0]), "+f"(acc[nt][1]),
                          "+f"(acc[nt][2]), "+f"(acc[nt][3])
                        : "r"(ah02.x), "r"(ah13.x), "r"(ah02.y), "r"(ah13.y),
                          "r"(bl[nt].x), "r"(bl[nt].y));
                }
            }
        }

        // epilogue: c0,c1 -> px gid; c2,c3 -> px gid+8; oc = nt*8 + qid*2 (+1)
        const int pxa = x0 + P0 + gid, pxb = pxa + 8;
        const size_t rbase = (size_t)(y0 + ry + 1) * IP + 1;
        #pragma unroll
        for (int nt = 0; nt < 8; nt++) {
            int oc0 = nt * 8 + qid * 2;
            float b0 = bn[oc0],       b1 = bn[oc0 + 1];
            float s0 = bn[64 + oc0],  s1 = bn[64 + oc0 + 1];
            float h0 = bn[128 + oc0], h1 = bn[128 + oc0 + 1];
            g_integ[(size_t)oc0       * IPP + rbase + pxa] = fmaxf(acc[nt][0] + b0, 0.f) * s0 + h0;
            g_integ[(size_t)(oc0 + 1) * IPP + rbase + pxa] = fmaxf(acc[nt][1] + b1, 0.f) * s1 + h1;
            g_integ[(size_t)oc0       * IPP + rbase + pxb] = fmaxf(acc[nt][2] + b0, 0.f) * s0 + h0;
            g_integ[(size_t)(oc0 + 1) * IPP + rbase + pxb] = fmaxf(acc[nt][3] + b1, 0.f) * s1 + h1;
        }
    }
}

// ---------------- row-wise inclusive scan (x), fp32, coalesced ----------------
__global__ __launch_bounds__(256) void rowscan_k() {
    const int warp = threadIdx.x >> 5, lane = threadIdx.x & 31;
    const int row = blockIdx.x * 8 + warp;
    const int c = row / HH, y = row % HH + 1;
    float* p = g_integ + (size_t)c * IPP + (size_t)y * IP + 1;

    float v[24];
    #pragma unroll
    for (int i = 0; i < 24; i++) v[i] = p[i * 32 + lane];

    float carry = 0.f;
    #pragma unroll
    for (int i = 0; i < 24; i++) {
        float x = v[i];
        #pragma unroll
        for (int d = 1; d < 32; d <<= 1) {
            float n = __shfl_up_sync(0xffffffffu, x, d);
            if (lane >= d) x += n;
        }
        x += carry;
        carry = __shfl_sync(0xffffffffu, x, 31);
        v[i] = x;
    }

    #pragma unroll
    for (int i = 0; i < 24; i++) p[i * 32 + lane] = v[i];
}

// ---------------- column-wise inclusive scan (y), fp32 ----------------
__global__ __launch_bounds__(256) void colscan_k() {
    int idx = blockIdx.x * 256 + threadIdx.x;
    if (idx >= 64 * WW) return;
    int c = idx / WW, x = idx % WW + 1;
    float* p = g_integ + (size_t)c * IPP + x;
    float s = 0.f;
    #pragma unroll 8
    for (int y = 1; y <= HH; y++) {
        s += p[(size_t)y * IP];
        p[(size_t)y * IP] = s;
    }
}

// ---------------- ROI pool + FC1(relu) + FC2 ----------------
__global__ __launch_bounds__(128) void roi_fc_k(
    const int* __restrict__ boxes,
    const float* __restrict__ fc1w, const float* __restrict__ fc1b,
    const float* __restrict__ fc2w, const float* __restrict__ fc2b,
    float* __restrict__ out)
{
    __shared__ float s_pool[1600];
    __shared__ float s_h1[128];
    __shared__ int sy0[5], sy1[5], sx0[5], sx1[5];

    const int b = blockIdx.x, tid = threadIdx.x;
    if (tid < 5) {
        int xmin = boxes[b*4+0], ymin = boxes[b*4+1];
        int xmax = boxes[b*4+2], ymax = boxes[b*4+3];
        int bh = ymax - ymin, bw = xmax - xmin;
        sy0[tid] = ymin + tid * bh / 5;
        sy1[tid] = ymin + ((tid + 1) * bh + 4) / 5;
        sx0[tid] = xmin + tid * bw / 5;
        sx1[tid] = xmin + ((tid + 1) * bw + 4) / 5;
    }
    __syncthreads();

    for (int idx = tid; idx < 1600; idx += 128) {
        int c = idx / 25, r = idx % 25, i = r / 5, j = r % 5;
        const float* I = g_integ + (size_t)c * IPP;
        double s = (double)I[(size_t)sy1[i] * IP + sx1[j]] - (double)I[(size_t)sy0[i] * IP + sx1[j]]
                 - (double)I[(size_t)sy1[i] * IP + sx0[j]] + (double)I[(size_t)sy0[i] * IP + sx0[j]];
        double area = (double)((sy1[i] - sy0[i]) * (sx1[j] - sx0[j]));
        s_pool[idx] = (float)(s / area);
    }
    __syncthreads();

    const int warp = tid >> 5, lane = tid & 31;
    for (int o = warp; o < 128; o += 4) {
        const float* wr = fc1w + o * 1600;
        float sum = 0.f;
        for (int k = lane; k < 1600; k += 32) sum = fmaf(wr[k], s_pool[k], sum);
        #pragma unroll
        for (int d = 16; d; d >>= 1) sum += __shfl_down_sync(0xffffffffu, sum, d);
        if (lane == 0) s_h1[o] = fmaxf(sum + fc1b[o], 0.f);
    }
    __syncthreads();

    {
        int o = warp;
        float sum = 0.f;
        #pragma unroll
        for (int k = lane; k < 128; k += 32) sum = fmaf(fc2w[o * 128 + k], s_h1[k], sum);
        #pragma unroll
        for (int d = 16; d; d >>= 1) sum += __shfl_down_sync(0xffffffffu, sum, d);
        if (lane == 0) out[b * 4 + o] = sum + fc2b[o];
    }
}

// ---------------- launch ----------------
extern "C" void kernel_launch(void* const* d_in, const int* in_sizes, int n_in,
                              void* d_out, int out_size)
{
    const float* image = (const float*)d_in[0];
    const int*   boxes = (const int*)  d_in[1];
    const float* c1w = (const float*)d_in[2];
    const float* c1b = (const float*)d_in[3];
    const float* b1g = (const float*)d_in[4];
    const float* b1b = (const float*)d_in[5];
    const float* b1m = (const float*)d_in[6];
    const float* b1v = (const float*)d_in[7];
    const float* c2w = (const float*)d_in[8];
    const float* c2b = (const float*)d_in[9];
    const float* b2g = (const float*)d_in[10];
    const float* b2b = (const float*)d_in[11];
    const float* b2m = (const float*)d_in[12];
    const float* b2v = (const float*)d_in[13];
    const float* f1w = (const float*)d_in[14];
    const float* f1b = (const float*)d_in[15];
    const float* f2w = (const float*)d_in[16];
    const float* f2b = (const float*)d_in[17];
    float* out = (float*)d_out;

    cudaFuncSetAttribute(conv2_k, cudaFuncAttributeMaxDynamicSharedMemorySize, SMEM_DYN);

    conv1_k<<<dim3(48, 48), dim3(16, 16)>>>(image, c1w, c1b, b1g, b1b, b1m, b1v);
    zborder_row_k<<<(64 * IP + 255) / 256, 256>>>();
    zborder_col_k<<<(64 * IP + 255) / 256, 256>>>();
    conv2_k<<<dim3(6, 192), 256, SMEM_DYN>>>(c2w, c2b, b2g, b2b, b2m, b2v);  // profiled slot
    rowscan_k<<<64 * HH / 8, 256>>>();
    colscan_k<<<(64 * WW + 255) / 256, 256>>>();
    roi_fc_k<<<512, 128>>>(boxes, f1w, f1b, f2w, f2b, out);
}